// round 3
// baseline (speedup 1.0000x reference)
#include <cuda_runtime.h>
#include <cuda_bf16.h>
#include <cstdint>
#include <cstddef>

// Problem constants
#define TT 32768      // tokens (B*S)
#define DD 512        // model dim
#define FF 2048       // ffn dim
#define EE 8          // experts
#define SLOTS 65536   // TT * K(=2)

// ---------------------------------------------------------------------------
// Device scratch (allocation-free rule: __device__ globals)
// 256B-aligned: cp.async 16B requires 16B-aligned global addresses.
// NOTE: these symbols are ONLY referenced from device code. Taking their
// address in host code yields the host shadow symbol — which GB300's ATS
// will happily read as zeros instead of faulting. (Round-2 root cause.)
// ---------------------------------------------------------------------------
__device__ __align__(256) int   g_e0[TT], g_e1[TT];
__device__ __align__(256) float g_w0t[TT], g_w1t[TT];
__device__ __align__(256) int   g_counts[EE];
__device__ __align__(256) int   g_offsets[EE + 1];
__device__ __align__(256) int   g_cursor[EE];
__device__ __align__(256) int   g_tile_e[528], g_tile_r0[528];
__device__ __align__(256) int   g_num_tiles;
__device__ __align__(256) int   g_slot_token[SLOTS];
__device__ __align__(256) float g_slot_w[SLOTS];

__device__ __align__(256) __nv_bfloat16 g_Xh[(size_t)TT * DD];
__device__ __align__(256) __nv_bfloat16 g_Xl[(size_t)TT * DD];
__device__ __align__(256) __nv_bfloat16 g_W1h[(size_t)EE * DD * FF];
__device__ __align__(256) __nv_bfloat16 g_W1l[(size_t)EE * DD * FF];
__device__ __align__(256) __nv_bfloat16 g_W2h[(size_t)EE * FF * DD];
__device__ __align__(256) __nv_bfloat16 g_W2l[(size_t)EE * FF * DD];
__device__ __align__(256) __nv_bfloat16 g_Hh[(size_t)SLOTS * FF];
__device__ __align__(256) __nv_bfloat16 g_Hl[(size_t)SLOTS * FF];

// ---------------------------------------------------------------------------
// PTX helpers
// ---------------------------------------------------------------------------
__device__ __forceinline__ uint32_t smem_u32(const void* p) {
    uint32_t a;
    asm("{ .reg .u64 t; cvta.to.shared.u64 t, %1; cvt.u32.u64 %0, t; }"
        : "=r"(a) : "l"(p));
    return a;
}

__device__ __forceinline__ void cp16(uint32_t s, const void* g, bool valid) {
    int sz = valid ? 16 : 0;
    asm volatile("cp.async.cg.shared.global [%0], [%1], 16, %2;\n"
                 :: "r"(s), "l"(__cvta_generic_to_global(g)), "r"(sz));
}

__device__ __forceinline__ void cp_commit() {
    asm volatile("cp.async.commit_group;\n" ::);
}
__device__ __forceinline__ void cp_wait1() {
    asm volatile("cp.async.wait_group 1;\n" ::);
}

__device__ __forceinline__ void ldsm_x4(uint32_t* r, uint32_t addr) {
    asm volatile("ldmatrix.sync.aligned.m8n8.x4.shared.b16 {%0,%1,%2,%3}, [%4];"
                 : "=r"(r[0]), "=r"(r[1]), "=r"(r[2]), "=r"(r[3]) : "r"(addr));
}
__device__ __forceinline__ void ldsm_x4_t(uint32_t* r, uint32_t addr) {
    asm volatile("ldmatrix.sync.aligned.m8n8.x4.trans.shared.b16 {%0,%1,%2,%3}, [%4];"
                 : "=r"(r[0]), "=r"(r[1]), "=r"(r[2]), "=r"(r[3]) : "r"(addr));
}

__device__ __forceinline__ void mma_bf16(float* d, const uint32_t* a,
                                         uint32_t b0, uint32_t b1) {
    asm volatile(
        "mma.sync.aligned.m16n8k16.row.col.f32.bf16.bf16.f32 "
        "{%0,%1,%2,%3}, {%4,%5,%6,%7}, {%8,%9}, {%0,%1,%2,%3};\n"
        : "+f"(d[0]), "+f"(d[1]), "+f"(d[2]), "+f"(d[3])
        : "r"(a[0]), "r"(a[1]), "r"(a[2]), "r"(a[3]), "r"(b0), "r"(b1));
}

// ---------------------------------------------------------------------------
// Router: logits = x @ Wr + br ; top-2 ; renormalized softmax weights
// ---------------------------------------------------------------------------
__global__ void k_router(const float* __restrict__ x,
                         const float* __restrict__ Wr,
                         const float* __restrict__ br) {
    __shared__ float sW[EE * DD];   // transposed: sW[e*512 + d]
    __shared__ float sbr[EE];
    const int tid = threadIdx.x;
    for (int i = tid; i < EE * DD; i += 256) {
        int e = i >> 9, d = i & 511;
        sW[i] = Wr[d * EE + e];
    }
    if (tid < EE) sbr[tid] = br[tid];
    __syncthreads();

    const int lane = tid & 31, wid = tid >> 5;
    const int t = blockIdx.x * 8 + wid;
    const float* xr = x + (size_t)t * DD;

    float a[EE];
#pragma unroll
    for (int e = 0; e < EE; e++) a[e] = 0.f;
#pragma unroll
    for (int i = 0; i < 16; i++) {
        float xv = xr[lane + 32 * i];
#pragma unroll
        for (int e = 0; e < EE; e++) a[e] += xv * sW[e * DD + lane + 32 * i];
    }
#pragma unroll
    for (int off = 16; off > 0; off >>= 1) {
#pragma unroll
        for (int e = 0; e < EE; e++)
            a[e] += __shfl_down_sync(0xffffffffu, a[e], off);
    }
    if (lane == 0) {
#pragma unroll
        for (int e = 0; e < EE; e++) a[e] += sbr[e];
        int e0 = 0; float m0 = a[0];
#pragma unroll
        for (int e = 1; e < EE; e++) if (a[e] > m0) { m0 = a[e]; e0 = e; }
        int e1 = -1; float m1 = -1e30f;
#pragma unroll
        for (int e = 0; e < EE; e++)
            if (e != e0 && a[e] > m1) { m1 = a[e]; e1 = e; }
        float d  = expf(m1 - m0);           // m1 <= m0
        float w0 = 1.f / (1.f + d);
        float w1 = d * w0;
        g_e0[t] = e0; g_e1[t] = e1;
        g_w0t[t] = w0; g_w1t[t] = w1;
        atomicAdd(&g_counts[e0], 1);
        atomicAdd(&g_counts[e1], 1);
    }
}

// ---------------------------------------------------------------------------
// Scan: offsets, cursors, per-expert tile table; reset counts for next launch
// ---------------------------------------------------------------------------
__global__ void k_scan() {
    int off = 0;
    for (int e = 0; e < EE; e++) {
        g_offsets[e] = off;
        g_cursor[e]  = off;
        off += g_counts[e];
        g_counts[e] = 0;
    }
    g_offsets[EE] = off;   // == SLOTS
    int nt = 0;
    for (int e = 0; e < EE; e++) {
        for (int r = g_offsets[e]; r < g_offsets[e + 1]; r += 128) {
            g_tile_e[nt]  = e;
            g_tile_r0[nt] = r;
            nt++;
        }
    }
    g_num_tiles = nt;
}

__global__ void k_scatter() {
    int t = blockIdx.x * 256 + threadIdx.x;
    int e0 = g_e0[t], e1 = g_e1[t];
    int p0 = atomicAdd(&g_cursor[e0], 1);
    g_slot_token[p0] = t; g_slot_w[p0] = g_w0t[t];
    int p1 = atomicAdd(&g_cursor[e1], 1);
    g_slot_token[p1] = t; g_slot_w[p1] = g_w1t[t];
}

// ---------------------------------------------------------------------------
// fp32 -> bf16 hi/lo split converters
// ---------------------------------------------------------------------------
__device__ __forceinline__ void split4(const float4 v,
                                       __nv_bfloat162& h01, __nv_bfloat162& h23,
                                       __nv_bfloat162& l01, __nv_bfloat162& l23) {
    __nv_bfloat16 h0 = __float2bfloat16_rn(v.x);
    __nv_bfloat16 h1 = __float2bfloat16_rn(v.y);
    __nv_bfloat16 h2 = __float2bfloat16_rn(v.z);
    __nv_bfloat16 h3 = __float2bfloat16_rn(v.w);
    __nv_bfloat16 l0 = __float2bfloat16_rn(v.x - __bfloat162float(h0));
    __nv_bfloat16 l1 = __float2bfloat16_rn(v.y - __bfloat162float(h1));
    __nv_bfloat16 l2 = __float2bfloat16_rn(v.z - __bfloat162float(h2));
    __nv_bfloat16 l3 = __float2bfloat16_rn(v.w - __bfloat162float(h3));
    h01.x = h0; h01.y = h1; h23.x = h2; h23.y = h3;
    l01.x = l0; l01.y = l1; l23.x = l2; l23.y = l3;
}

__global__ void k_convert_x(const float* __restrict__ x) {
    size_t i = ((size_t)blockIdx.x * 256 + threadIdx.x) * 4;
    float4 v = *reinterpret_cast<const float4*>(x + i);
    __nv_bfloat162 h01, h23, l01, l23;
    split4(v, h01, h23, l01, l23);
    *reinterpret_cast<__nv_bfloat162*>(g_Xh + i)     = h01;
    *reinterpret_cast<__nv_bfloat162*>(g_Xh + i + 2) = h23;
    *reinterpret_cast<__nv_bfloat162*>(g_Xl + i)     = l01;
    *reinterpret_cast<__nv_bfloat162*>(g_Xl + i + 2) = l23;
}

__global__ void k_convert_w(const float* __restrict__ W1,
                            const float* __restrict__ W2) {
    size_t i = ((size_t)blockIdx.x * 256 + threadIdx.x) * 4;
    const size_t W1N = (size_t)EE * DD * FF;
    const float* src; __nv_bfloat16 *dh, *dl; size_t j;
    if (i < W1N) { src = W1; j = i;        dh = g_W1h; dl = g_W1l; }
    else         { src = W2; j = i - W1N;  dh = g_W2h; dl = g_W2l; }
    float4 v = *reinterpret_cast<const float4*>(src + j);
    __nv_bfloat162 h01, h23, l01, l23;
    split4(v, h01, h23, l01, l23);
    *reinterpret_cast<__nv_bfloat162*>(dh + j)     = h01;
    *reinterpret_cast<__nv_bfloat162*>(dh + j + 2) = h23;
    *reinterpret_cast<__nv_bfloat162*>(dl + j)     = l01;
    *reinterpret_cast<__nv_bfloat162*>(dl + j + 2) = l23;
}

__global__ void k_zero(float* __restrict__ out) {
    size_t i = ((size_t)blockIdx.x * 256 + threadIdx.x) * 4;
    *reinterpret_cast<float4*>(out + i) = make_float4(0.f, 0.f, 0.f, 0.f);
}

// ---------------------------------------------------------------------------
// Grouped GEMM. MODE 0: H = relu(Xg @ W1[e] + b1[e]) -> bf16 hi/lo scratch
//               MODE 1: out[token] += w * (H @ W2[e] + b2[e])   (atomicAdd)
// Weight/activation scratch pointers are taken from the __device__ globals
// INSIDE the kernel (device code) — never passed from host.
// Tile: BM=128, BN=128, BK=64. 256 threads = 8 warps (2m x 4n), warp 64x32.
// bf16 hi/lo split: 3 MMAs per (hi,lo) pair -> ~fp32 accuracy.
// XOR swizzle on 16B chunks -> conflict-free ldmatrix.
// ---------------------------------------------------------------------------
constexpr int SMEM_BYTES = 131072;

template <int MODE>
__global__ void __launch_bounds__(256, 1) k_gemm(
    const float* __restrict__ bias, float* __restrict__ out) {
    constexpr int KDIM = MODE ? FF : DD;
    constexpr int NDIM = MODE ? DD : FF;
    constexpr int KT   = KDIM / 64;

    const int bid = blockIdx.x;
    if (bid >= g_num_tiles) return;
    const int e       = g_tile_e[bid];
    const int row0    = g_tile_r0[bid];
    const int seg_end = g_offsets[e + 1];
    const int n0      = blockIdx.y * 128;

    extern __shared__ char smem[];
    const uint32_t sA0 = smem_u32(smem);
    const uint32_t sB0 = sA0 + 65536;

    const int tid = threadIdx.x;
    const int lane = tid & 31, wid = tid >> 5;
    const int wm = wid >> 2, wn = wid & 3;

    const __nv_bfloat16* Ah = MODE ? g_Hh  : g_Xh;
    const __nv_bfloat16* Al = MODE ? g_Hl  : g_Xl;
    const __nv_bfloat16* Bh = MODE ? g_W2h : g_W1h;
    const __nv_bfloat16* Bl = MODE ? g_W2l : g_W1l;

    auto load_stage = [&](int ko, int st) {
        const int k0 = ko * 64;
        // A: 128 rows x (8 hi + 8 lo) 16B chunks = 2048 chunks, 8/thread
#pragma unroll
        for (int i = 0; i < 8; i++) {
            int c2   = tid + i * 256;
            int row  = c2 >> 4;
            int w16  = c2 & 15;
            int part = w16 >> 3;
            int kc   = w16 & 7;
            int phys = (part << 3) | ((kc ^ row) & 7);
            uint32_t s = sA0 + ((((st << 7) + row) << 4) + phys) * 16;
            int rg  = row0 + row;
            bool v  = rg < seg_end;
            size_t aidx;
            if (MODE == 0) {
                int tok = v ? g_slot_token[rg] : 0;
                aidx = (size_t)tok * DD + k0 + (kc << 3);
            } else {
                aidx = (size_t)(v ? rg : 0) * FF + k0 + (kc << 3);
            }
            cp16(s, (part ? Al : Ah) + aidx, v);
        }
        // B: 64 k-rows x (16 hi + 16 lo) chunks = 2048 chunks, 8/thread
#pragma unroll
        for (int i = 0; i < 8; i++) {
            int c2   = tid + i * 256;
            int kr   = c2 >> 5;
            int w32  = c2 & 31;
            int part = w32 >> 4;
            int nc   = w32 & 15;
            int phys = (part << 4) | (nc & 8) | ((nc ^ kr) & 7);
            uint32_t s = sB0 + ((((st << 6) + kr) << 5) + phys) * 16;
            size_t bidx = (size_t)e * KDIM * NDIM + (size_t)(k0 + kr) * NDIM
                        + n0 + (nc << 3);
            cp16(s, (part ? Bl : Bh) + bidx, true);
        }
        cp_commit();
    };

    float acc[4][4][4];
#pragma unroll
    for (int a = 0; a < 4; a++)
#pragma unroll
        for (int b = 0; b < 4; b++)
#pragma unroll
            for (int c = 0; c < 4; c++) acc[a][b][c] = 0.f;

    load_stage(0, 0);
    int st = 0;
    for (int ko = 0; ko < KT; ko++) {
        if (ko + 1 < KT) load_stage(ko + 1, st ^ 1);
        else cp_commit();   // empty group so wait_group 1 drains the real one
        cp_wait1();
        __syncthreads();

#pragma unroll
        for (int ks = 0; ks < 4; ks++) {
            uint32_t afh[4][4], afl[4][4];
#pragma unroll
            for (int mt = 0; mt < 4; mt++) {
                int r  = wm * 64 + mt * 16 + (lane & 15);
                int kc = ks * 2 + (lane >> 4);
                int ph = (kc ^ r) & 7;
                uint32_t ah = sA0 + ((((st << 7) + r) << 4) + ph) * 16;
                ldsm_x4(afh[mt], ah);
                ldsm_x4(afl[mt], ah + 128);   // lo part: +8 chunks
            }
            uint32_t bh[8], bl[8];
#pragma unroll
            for (int h = 0; h < 2; h++) {
                int kr   = ks * 16 + (lane & 15);
                int ncnk = wn * 4 + h * 2 + (lane >> 4);
                int ph   = (ncnk & 8) | ((ncnk ^ kr) & 7);
                uint32_t b0 = sB0 + ((((st << 6) + kr) << 5) + ph) * 16;
                ldsm_x4_t(&bh[h * 4], b0);
                ldsm_x4_t(&bl[h * 4], b0 + 256);  // lo part: +16 chunks
            }
#pragma unroll
            for (int mt = 0; mt < 4; mt++)
#pragma unroll
                for (int nt = 0; nt < 4; nt++) {
                    int idx = (nt >> 1) * 4 + (nt & 1) * 2;
                    mma_bf16(acc[mt][nt], afh[mt], bh[idx], bh[idx + 1]);
                    mma_bf16(acc[mt][nt], afh[mt], bl[idx], bl[idx + 1]);
                    mma_bf16(acc[mt][nt], afl[mt], bh[idx], bh[idx + 1]);
                }
        }
        __syncthreads();
        st ^= 1;
    }

    // Epilogue
    if (MODE == 0) {
#pragma unroll
        for (int mt = 0; mt < 4; mt++) {
            int rr = wm * 64 + mt * 16 + (lane >> 2);
#pragma unroll
            for (int i = 0; i < 2; i++) {
                int rg = row0 + rr + i * 8;
                if (rg < seg_end) {
                    size_t base = (size_t)rg * FF;
#pragma unroll
                    for (int nt = 0; nt < 4; nt++) {
                        int col = n0 + wn * 32 + nt * 8 + ((lane & 3) << 1);
                        float v0 = acc[mt][nt][i * 2 + 0] + bias[e * FF + col];
                        float v1 = acc[mt][nt][i * 2 + 1] + bias[e * FF + col + 1];
                        v0 = fmaxf(v0, 0.f);
                        v1 = fmaxf(v1, 0.f);
                        __nv_bfloat16 h0 = __float2bfloat16_rn(v0);
                        __nv_bfloat16 h1 = __float2bfloat16_rn(v1);
                        __nv_bfloat16 l0 = __float2bfloat16_rn(v0 - __bfloat162float(h0));
                        __nv_bfloat16 l1 = __float2bfloat16_rn(v1 - __bfloat162float(h1));
                        __nv_bfloat162 hp; hp.x = h0; hp.y = h1;
                        __nv_bfloat162 lp; lp.x = l0; lp.y = l1;
                        *reinterpret_cast<__nv_bfloat162*>(g_Hh + base + col) = hp;
                        *reinterpret_cast<__nv_bfloat162*>(g_Hl + base + col) = lp;
                    }
                }
            }
        }
    } else {
#pragma unroll
        for (int mt = 0; mt < 4; mt++) {
            int rr = wm * 64 + mt * 16 + (lane >> 2);
#pragma unroll
            for (int i = 0; i < 2; i++) {
                int rg = row0 + rr + i * 8;
                if (rg < seg_end) {
                    int tok = g_slot_token[rg];
                    float w = g_slot_w[rg];
                    float* orow = out + (size_t)tok * DD;
#pragma unroll
                    for (int nt = 0; nt < 4; nt++) {
                        int col = n0 + wn * 32 + nt * 8 + ((lane & 3) << 1);
                        float v0 = (acc[mt][nt][i * 2 + 0] + bias[e * DD + col]) * w;
                        float v1 = (acc[mt][nt][i * 2 + 1] + bias[e * DD + col + 1]) * w;
                        atomicAdd(orow + col, v0);
                        atomicAdd(orow + col + 1, v1);
                    }
                }
            }
        }
    }
}

// ---------------------------------------------------------------------------
// Launch
// ---------------------------------------------------------------------------
extern "C" void kernel_launch(void* const* d_in, const int* in_sizes, int n_in,
                              void* d_out, int out_size) {
    const float* x  = (const float*)d_in[0];
    const float* Wr = (const float*)d_in[1];
    const float* br = (const float*)d_in[2];
    const float* W1 = (const float*)d_in[3];
    const float* b1 = (const float*)d_in[4];
    const float* W2 = (const float*)d_in[5];
    const float* b2 = (const float*)d_in[6];
    float* out = (float*)d_out;

    cudaFuncSetAttribute(k_gemm<0>, cudaFuncAttributeMaxDynamicSharedMemorySize,
                         SMEM_BYTES);
    cudaFuncSetAttribute(k_gemm<1>, cudaFuncAttributeMaxDynamicSharedMemorySize,
                         SMEM_BYTES);

    k_router<<<TT / 8, 256>>>(x, Wr, br);
    k_scan<<<1, 1>>>();
    k_scatter<<<TT / 256, 256>>>();
    k_convert_x<<<(TT * DD / 4) / 256, 256>>>(x);
    k_convert_w<<<(2 * EE * DD * FF / 4) / 256, 256>>>(W1, W2);
    k_zero<<<(TT * DD / 4) / 256, 256>>>(out);

    // GEMM1: 65536 x 2048, K=512 (grouped by expert)
    k_gemm<0><<<dim3(520, FF / 128), 256, SMEM_BYTES>>>(b1, nullptr);
    // GEMM2: 65536 x 512, K=2048 (grouped), scaled atomic accumulate
    k_gemm<1><<<dim3(520, DD / 128), 256, SMEM_BYTES>>>(b2, out);
}

// round 4
// speedup vs baseline: 1.5059x; 1.5059x over previous
#include <cuda_runtime.h>
#include <cuda_fp16.h>
#include <cstdint>
#include <cstddef>

// Problem constants
#define TT 32768      // tokens (B*S)
#define DD 512        // model dim
#define FF 2048       // ffn dim
#define EE 8          // experts
#define SLOTS 65536   // TT * K(=2)

// ---------------------------------------------------------------------------
// Device scratch (allocation-free rule: __device__ globals).
// Referenced ONLY from device code (host use would hit ATS host-shadow zeros).
// ---------------------------------------------------------------------------
__device__ __align__(256) int   g_e0[TT], g_e1[TT];
__device__ __align__(256) float g_w0t[TT], g_w1t[TT];
__device__ __align__(256) int   g_counts[EE];
__device__ __align__(256) int   g_offsets[EE + 1];
__device__ __align__(256) int   g_cursor[EE];
__device__ __align__(256) int   g_tile_e[528], g_tile_r0[528];
__device__ __align__(256) int   g_num_tiles;
__device__ __align__(256) int   g_slot_token[SLOTS];
__device__ __align__(256) float g_slot_w[SLOTS];

// fp16 operand scratch: A-side single precision (X, H), B-side hi/lo (W1, W2)
__device__ __align__(256) __half g_X [(size_t)TT * DD];
__device__ __align__(256) __half g_W1h[(size_t)EE * DD * FF];
__device__ __align__(256) __half g_W1l[(size_t)EE * DD * FF];
__device__ __align__(256) __half g_W2h[(size_t)EE * FF * DD];
__device__ __align__(256) __half g_W2l[(size_t)EE * FF * DD];
__device__ __align__(256) __half g_H [(size_t)SLOTS * FF];

// ---------------------------------------------------------------------------
// PTX helpers
// ---------------------------------------------------------------------------
__device__ __forceinline__ uint32_t smem_u32(const void* p) {
    uint32_t a;
    asm("{ .reg .u64 t; cvta.to.shared.u64 t, %1; cvt.u32.u64 %0, t; }"
        : "=r"(a) : "l"(p));
    return a;
}

__device__ __forceinline__ void cp16(uint32_t s, const void* g, bool valid) {
    int sz = valid ? 16 : 0;
    asm volatile("cp.async.cg.shared.global [%0], [%1], 16, %2;\n"
                 :: "r"(s), "l"(__cvta_generic_to_global(g)), "r"(sz));
}

__device__ __forceinline__ void cp_commit() {
    asm volatile("cp.async.commit_group;\n" ::);
}
__device__ __forceinline__ void cp_wait1() {
    asm volatile("cp.async.wait_group 1;\n" ::);
}

__device__ __forceinline__ void ldsm_x4(uint32_t* r, uint32_t addr) {
    asm volatile("ldmatrix.sync.aligned.m8n8.x4.shared.b16 {%0,%1,%2,%3}, [%4];"
                 : "=r"(r[0]), "=r"(r[1]), "=r"(r[2]), "=r"(r[3]) : "r"(addr));
}
__device__ __forceinline__ void ldsm_x4_t(uint32_t* r, uint32_t addr) {
    asm volatile("ldmatrix.sync.aligned.m8n8.x4.trans.shared.b16 {%0,%1,%2,%3}, [%4];"
                 : "=r"(r[0]), "=r"(r[1]), "=r"(r[2]), "=r"(r[3]) : "r"(addr));
}

__device__ __forceinline__ void mma_f16(float* d, const uint32_t* a,
                                        uint32_t b0, uint32_t b1) {
    asm volatile(
        "mma.sync.aligned.m16n8k16.row.col.f32.f16.f16.f32 "
        "{%0,%1,%2,%3}, {%4,%5,%6,%7}, {%8,%9}, {%0,%1,%2,%3};\n"
        : "+f"(d[0]), "+f"(d[1]), "+f"(d[2]), "+f"(d[3])
        : "r"(a[0]), "r"(a[1]), "r"(a[2]), "r"(a[3]), "r"(b0), "r"(b1));
}

// ---------------------------------------------------------------------------
// Router: logits = x @ Wr + br ; top-2 ; renormalized softmax weights
// ---------------------------------------------------------------------------
__global__ void k_router(const float* __restrict__ x,
                         const float* __restrict__ Wr,
                         const float* __restrict__ br) {
    __shared__ float sW[EE * DD];   // transposed: sW[e*512 + d]
    __shared__ float sbr[EE];
    const int tid = threadIdx.x;
    for (int i = tid; i < EE * DD; i += 256) {
        int e = i >> 9, d = i & 511;
        sW[i] = Wr[d * EE + e];
    }
    if (tid < EE) sbr[tid] = br[tid];
    __syncthreads();

    const int lane = tid & 31, wid = tid >> 5;
    const int t = blockIdx.x * 8 + wid;
    const float* xr = x + (size_t)t * DD;

    float a[EE];
#pragma unroll
    for (int e = 0; e < EE; e++) a[e] = 0.f;
#pragma unroll
    for (int i = 0; i < 16; i++) {
        float xv = xr[lane + 32 * i];
#pragma unroll
        for (int e = 0; e < EE; e++) a[e] += xv * sW[e * DD + lane + 32 * i];
    }
#pragma unroll
    for (int off = 16; off > 0; off >>= 1) {
#pragma unroll
        for (int e = 0; e < EE; e++)
            a[e] += __shfl_down_sync(0xffffffffu, a[e], off);
    }
    if (lane == 0) {
#pragma unroll
        for (int e = 0; e < EE; e++) a[e] += sbr[e];
        int e0 = 0; float m0 = a[0];
#pragma unroll
        for (int e = 1; e < EE; e++) if (a[e] > m0) { m0 = a[e]; e0 = e; }
        int e1 = -1; float m1 = -1e30f;
#pragma unroll
        for (int e = 0; e < EE; e++)
            if (e != e0 && a[e] > m1) { m1 = a[e]; e1 = e; }
        float d  = expf(m1 - m0);           // m1 <= m0
        float w0 = 1.f / (1.f + d);
        float w1 = d * w0;
        g_e0[t] = e0; g_e1[t] = e1;
        g_w0t[t] = w0; g_w1t[t] = w1;
        atomicAdd(&g_counts[e0], 1);
        atomicAdd(&g_counts[e1], 1);
    }
}

// ---------------------------------------------------------------------------
// Scan + scatter (expert-grouped slot lists, static tile table)
// ---------------------------------------------------------------------------
__global__ void k_scan() {
    int off = 0;
    for (int e = 0; e < EE; e++) {
        g_offsets[e] = off;
        g_cursor[e]  = off;
        off += g_counts[e];
        g_counts[e] = 0;
    }
    g_offsets[EE] = off;   // == SLOTS
    int nt = 0;
    for (int e = 0; e < EE; e++) {
        for (int r = g_offsets[e]; r < g_offsets[e + 1]; r += 128) {
            g_tile_e[nt]  = e;
            g_tile_r0[nt] = r;
            nt++;
        }
    }
    g_num_tiles = nt;
}

__global__ void k_scatter() {
    int t = blockIdx.x * 256 + threadIdx.x;
    int e0 = g_e0[t], e1 = g_e1[t];
    int p0 = atomicAdd(&g_cursor[e0], 1);
    g_slot_token[p0] = t; g_slot_w[p0] = g_w0t[t];
    int p1 = atomicAdd(&g_cursor[e1], 1);
    g_slot_token[p1] = t; g_slot_w[p1] = g_w1t[t];
}

// ---------------------------------------------------------------------------
// Converters
// ---------------------------------------------------------------------------
__global__ void k_convert_x(const float* __restrict__ x) {
    size_t i = ((size_t)blockIdx.x * 256 + threadIdx.x) * 4;
    float4 v = *reinterpret_cast<const float4*>(x + i);
    __half2 a; a.x = __float2half_rn(v.x); a.y = __float2half_rn(v.y);
    __half2 b; b.x = __float2half_rn(v.z); b.y = __float2half_rn(v.w);
    *reinterpret_cast<__half2*>(g_X + i)     = a;
    *reinterpret_cast<__half2*>(g_X + i + 2) = b;
}

__global__ void k_convert_w(const float* __restrict__ W1,
                            const float* __restrict__ W2) {
    size_t i = ((size_t)blockIdx.x * 256 + threadIdx.x) * 4;
    const size_t W1N = (size_t)EE * DD * FF;
    const float* src; __half *dh, *dl; size_t j;
    if (i < W1N) { src = W1; j = i;        dh = g_W1h; dl = g_W1l; }
    else         { src = W2; j = i - W1N;  dh = g_W2h; dl = g_W2l; }
    float4 v = *reinterpret_cast<const float4*>(src + j);
    __half h0 = __float2half_rn(v.x), h1 = __float2half_rn(v.y);
    __half h2 = __float2half_rn(v.z), h3 = __float2half_rn(v.w);
    __half l0 = __float2half_rn(v.x - __half2float(h0));
    __half l1 = __float2half_rn(v.y - __half2float(h1));
    __half l2 = __float2half_rn(v.z - __half2float(h2));
    __half l3 = __float2half_rn(v.w - __half2float(h3));
    __half2 hp0; hp0.x = h0; hp0.y = h1;
    __half2 hp1; hp1.x = h2; hp1.y = h3;
    __half2 lp0; lp0.x = l0; lp0.y = l1;
    __half2 lp1; lp1.x = l2; lp1.y = l3;
    *reinterpret_cast<__half2*>(dh + j)     = hp0;
    *reinterpret_cast<__half2*>(dh + j + 2) = hp1;
    *reinterpret_cast<__half2*>(dl + j)     = lp0;
    *reinterpret_cast<__half2*>(dl + j + 2) = lp1;
}

__global__ void k_zero(float* __restrict__ out) {
    size_t i = ((size_t)blockIdx.x * 256 + threadIdx.x) * 4;
    *reinterpret_cast<float4*>(out + i) = make_float4(0.f, 0.f, 0.f, 0.f);
}

// ---------------------------------------------------------------------------
// Grouped GEMM. MODE 0: H = relu(Xg @ W1[e] + b1[e]) -> fp16 scratch
//               MODE 1: out[token] += w * (H @ W2[e] + b2[e])   (atomicAdd)
// Tile: BM=128, BN=256, BK=64. 512 threads = 16 warps (4m x 4n), warp 32x64.
// A: single fp16 (exact products, fp32 accum). B: fp16 hi/lo -> 2 MMAs.
// Smem/stage: A 16KB + B 64KB; 2 stages = 160KB.
// XOR swizzle on 16B chunks -> conflict-free ldmatrix.
// ---------------------------------------------------------------------------
constexpr int SMEM_BYTES = 163840;

template <int MODE>
__global__ void __launch_bounds__(512, 1) k_gemm(
    const float* __restrict__ bias, float* __restrict__ out) {
    constexpr int KDIM = MODE ? FF : DD;
    constexpr int NDIM = MODE ? DD : FF;
    constexpr int KT   = KDIM / 64;

    const int bid = blockIdx.x;
    if (bid >= g_num_tiles) return;
    const int e       = g_tile_e[bid];
    const int row0    = g_tile_r0[bid];
    const int seg_end = g_offsets[e + 1];
    const int n0      = blockIdx.y * 256;

    extern __shared__ char smem[];
    const uint32_t sA0 = smem_u32(smem);          // 2 x 16KB
    const uint32_t sB0 = sA0 + 32768;             // 2 x 64KB

    const int tid = threadIdx.x;
    const int lane = tid & 31, wid = tid >> 5;
    const int wm = wid >> 2, wn = wid & 3;        // 4 x 4 warps

    const __half* A  = MODE ? g_H   : g_X;
    const __half* Bh = MODE ? g_W2h : g_W1h;
    const __half* Bl = MODE ? g_W2l : g_W1l;

    auto load_stage = [&](int ko, int st) {
        const int k0 = ko * 64;
        // A: 128 rows x 8 chunks (64 fp16 = 128B/row) = 1024 chunks, 2/thread
#pragma unroll
        for (int i = 0; i < 2; i++) {
            int c    = tid + i * 512;
            int row  = c >> 3;
            int kc   = c & 7;
            int phys = (kc ^ row) & 7;
            uint32_t s = sA0 + ((((st << 7) + row) << 3) + phys) * 16;
            int rg  = row0 + row;
            bool v  = rg < seg_end;
            size_t aidx;
            if (MODE == 0) {
                int tok = v ? g_slot_token[rg] : 0;
                aidx = (size_t)tok * DD + k0 + (kc << 3);
            } else {
                aidx = (size_t)(v ? rg : 0) * FF + k0 + (kc << 3);
            }
            cp16(s, A + aidx, v);
        }
        // B: 64 k-rows x (32 hi + 32 lo) chunks = 4096 chunks, 8/thread
#pragma unroll
        for (int i = 0; i < 8; i++) {
            int c    = tid + i * 512;
            int kr   = c >> 6;
            int w64  = c & 63;
            int part = w64 >> 5;
            int nc   = w64 & 31;
            int phys = (nc & 24) | ((nc ^ kr) & 7);
            uint32_t s = sB0 + (((st << 12) + (kr << 6) + (part << 5) + phys)) * 16;
            size_t bidx = (size_t)e * KDIM * NDIM + (size_t)(k0 + kr) * NDIM
                        + n0 + (nc << 3);
            cp16(s, (part ? Bl : Bh) + bidx, true);
        }
        cp_commit();
    };

    float acc[2][8][4];
#pragma unroll
    for (int a = 0; a < 2; a++)
#pragma unroll
        for (int b = 0; b < 8; b++)
#pragma unroll
            for (int c = 0; c < 4; c++) acc[a][b][c] = 0.f;

    load_stage(0, 0);
    int st = 0;
    for (int ko = 0; ko < KT; ko++) {
        if (ko + 1 < KT) load_stage(ko + 1, st ^ 1);
        else cp_commit();   // empty group so wait_group 1 drains the real one
        cp_wait1();
        __syncthreads();

#pragma unroll
        for (int ks = 0; ks < 4; ks++) {
            uint32_t af[2][4];
#pragma unroll
            for (int mt = 0; mt < 2; mt++) {
                int r  = wm * 32 + mt * 16 + (lane & 15);
                int kc = ks * 2 + (lane >> 4);
                int ph = (kc ^ r) & 7;
                ldsm_x4(af[mt], sA0 + ((((st << 7) + r) << 3) + ph) * 16);
            }
#pragma unroll
            for (int part = 0; part < 2; part++) {
                uint32_t bf[16];
#pragma unroll
                for (int g = 0; g < 4; g++) {
                    int kr = ks * 16 + (lane & 15);
                    int nc = wn * 8 + g * 2 + (lane >> 4);
                    int ph = (nc & 24) | ((nc ^ kr) & 7);
                    ldsm_x4_t(&bf[g * 4],
                        sB0 + (((st << 12) + (kr << 6) + (part << 5) + ph)) * 16);
                }
#pragma unroll
                for (int mt = 0; mt < 2; mt++)
#pragma unroll
                    for (int nt = 0; nt < 8; nt++) {
                        int idx = (nt >> 1) * 4 + (nt & 1) * 2;
                        mma_f16(acc[mt][nt], af[mt], bf[idx], bf[idx + 1]);
                    }
            }
        }
        __syncthreads();
        st ^= 1;
    }

    // Epilogue
#pragma unroll
    for (int mt = 0; mt < 2; mt++) {
        int rr = wm * 32 + mt * 16 + (lane >> 2);
#pragma unroll
        for (int i = 0; i < 2; i++) {
            int rg = row0 + rr + i * 8;
            if (rg < seg_end) {
                if (MODE == 0) {
                    size_t base = (size_t)rg * FF;
#pragma unroll
                    for (int nt = 0; nt < 8; nt++) {
                        int col = n0 + wn * 64 + nt * 8 + ((lane & 3) << 1);
                        float v0 = acc[mt][nt][i * 2 + 0] + bias[e * NDIM + col];
                        float v1 = acc[mt][nt][i * 2 + 1] + bias[e * NDIM + col + 1];
                        __half2 hp;
                        hp.x = __float2half_rn(fmaxf(v0, 0.f));
                        hp.y = __float2half_rn(fmaxf(v1, 0.f));
                        *reinterpret_cast<__half2*>(g_H + base + col) = hp;
                    }
                } else {
                    int tok = g_slot_token[rg];
                    float w = g_slot_w[rg];
                    float* orow = out + (size_t)tok * DD;
#pragma unroll
                    for (int nt = 0; nt < 8; nt++) {
                        int col = n0 + wn * 64 + nt * 8 + ((lane & 3) << 1);
                        float v0 = (acc[mt][nt][i * 2 + 0] + bias[e * NDIM + col]) * w;
                        float v1 = (acc[mt][nt][i * 2 + 1] + bias[e * NDIM + col + 1]) * w;
                        atomicAdd(orow + col, v0);
                        atomicAdd(orow + col + 1, v1);
                    }
                }
            }
        }
    }
}

// ---------------------------------------------------------------------------
// Launch
// ---------------------------------------------------------------------------
extern "C" void kernel_launch(void* const* d_in, const int* in_sizes, int n_in,
                              void* d_out, int out_size) {
    const float* x  = (const float*)d_in[0];
    const float* Wr = (const float*)d_in[1];
    const float* br = (const float*)d_in[2];
    const float* W1 = (const float*)d_in[3];
    const float* b1 = (const float*)d_in[4];
    const float* W2 = (const float*)d_in[5];
    const float* b2 = (const float*)d_in[6];
    float* out = (float*)d_out;

    cudaFuncSetAttribute(k_gemm<0>, cudaFuncAttributeMaxDynamicSharedMemorySize,
                         SMEM_BYTES);
    cudaFuncSetAttribute(k_gemm<1>, cudaFuncAttributeMaxDynamicSharedMemorySize,
                         SMEM_BYTES);

    k_router<<<TT / 8, 256>>>(x, Wr, br);
    k_scan<<<1, 1>>>();
    k_scatter<<<TT / 256, 256>>>();
    k_convert_x<<<(TT * DD / 4) / 256, 256>>>(x);
    k_convert_w<<<(2 * EE * DD * FF / 4) / 256, 256>>>(W1, W2);
    k_zero<<<(TT * DD / 4) / 256, 256>>>(out);

    // GEMM1: 65536 x 2048, K=512 (grouped by expert)
    k_gemm<0><<<dim3(520, FF / 256), 512, SMEM_BYTES>>>(b1, nullptr);
    // GEMM2: 65536 x 512, K=2048 (grouped), scaled atomic accumulate
    k_gemm<1><<<dim3(520, DD / 256), 512, SMEM_BYTES>>>(b2, out);
}

// round 5
// speedup vs baseline: 2.3910x; 1.5877x over previous
#include <cuda_runtime.h>
#include <cuda_fp16.h>
#include <cstdint>
#include <cstddef>

// Problem constants
#define TT 32768      // tokens (B*S)
#define DD 512        // model dim
#define FF 2048       // ffn dim
#define EE 8          // experts
#define SLOTS 65536   // TT * K(=2)

// ---------------------------------------------------------------------------
// Device scratch (allocation-free rule: __device__ globals).
// Referenced ONLY from device code (host use would hit ATS host-shadow zeros).
// ---------------------------------------------------------------------------
__device__ __align__(256) int   g_e0[TT], g_e1[TT];
__device__ __align__(256) float g_w0t[TT], g_w1t[TT];
__device__ __align__(256) int   g_counts[EE];
__device__ __align__(256) int   g_offsets[EE + 1];
__device__ __align__(256) int   g_cursor[EE];
__device__ __align__(256) int   g_tile_e[528], g_tile_r0[528];
__device__ __align__(256) int   g_num_tiles;
__device__ __align__(256) int   g_slot_token[SLOTS];
__device__ __align__(256) float g_slot_w[SLOTS];

// fp16 operand scratch (all single precision; fp32 accumulate in MMA)
__device__ __align__(256) __half g_X [(size_t)TT * DD];
__device__ __align__(256) __half g_W1[(size_t)EE * DD * FF];
__device__ __align__(256) __half g_W2[(size_t)EE * FF * DD];
__device__ __align__(256) __half g_H [(size_t)SLOTS * FF];

// ---------------------------------------------------------------------------
// PTX helpers
// ---------------------------------------------------------------------------
__device__ __forceinline__ uint32_t smem_u32(const void* p) {
    uint32_t a;
    asm("{ .reg .u64 t; cvta.to.shared.u64 t, %1; cvt.u32.u64 %0, t; }"
        : "=r"(a) : "l"(p));
    return a;
}

__device__ __forceinline__ void cp16(uint32_t s, const void* g, bool valid) {
    int sz = valid ? 16 : 0;
    asm volatile("cp.async.cg.shared.global [%0], [%1], 16, %2;\n"
                 :: "r"(s), "l"(__cvta_generic_to_global(g)), "r"(sz));
}

__device__ __forceinline__ void cp_commit() {
    asm volatile("cp.async.commit_group;\n" ::);
}
__device__ __forceinline__ void cp_wait1() {
    asm volatile("cp.async.wait_group 1;\n" ::);
}

__device__ __forceinline__ void ldsm_x4(uint32_t* r, uint32_t addr) {
    asm volatile("ldmatrix.sync.aligned.m8n8.x4.shared.b16 {%0,%1,%2,%3}, [%4];"
                 : "=r"(r[0]), "=r"(r[1]), "=r"(r[2]), "=r"(r[3]) : "r"(addr));
}
__device__ __forceinline__ void ldsm_x4_t(uint32_t* r, uint32_t addr) {
    asm volatile("ldmatrix.sync.aligned.m8n8.x4.trans.shared.b16 {%0,%1,%2,%3}, [%4];"
                 : "=r"(r[0]), "=r"(r[1]), "=r"(r[2]), "=r"(r[3]) : "r"(addr));
}

__device__ __forceinline__ void mma_f16(float* d, const uint32_t* a,
                                        uint32_t b0, uint32_t b1) {
    asm volatile(
        "mma.sync.aligned.m16n8k16.row.col.f32.f16.f16.f32 "
        "{%0,%1,%2,%3}, {%4,%5,%6,%7}, {%8,%9}, {%0,%1,%2,%3};\n"
        : "+f"(d[0]), "+f"(d[1]), "+f"(d[2]), "+f"(d[3])
        : "r"(a[0]), "r"(a[1]), "r"(a[2]), "r"(a[3]), "r"(b0), "r"(b1));
}

// ---------------------------------------------------------------------------
// Router: logits = x @ Wr + br ; top-2 ; renormalized softmax weights
// ---------------------------------------------------------------------------
__global__ void k_router(const float* __restrict__ x,
                         const float* __restrict__ Wr,
                         const float* __restrict__ br) {
    __shared__ float sW[EE * DD];   // transposed: sW[e*512 + d]
    __shared__ float sbr[EE];
    const int tid = threadIdx.x;
    for (int i = tid; i < EE * DD; i += 256) {
        int e = i >> 9, d = i & 511;
        sW[i] = Wr[d * EE + e];
    }
    if (tid < EE) sbr[tid] = br[tid];
    __syncthreads();

    const int lane = tid & 31, wid = tid >> 5;
    const int t = blockIdx.x * 8 + wid;
    const float* xr = x + (size_t)t * DD;

    float a[EE];
#pragma unroll
    for (int e = 0; e < EE; e++) a[e] = 0.f;
#pragma unroll
    for (int i = 0; i < 16; i++) {
        float xv = xr[lane + 32 * i];
#pragma unroll
        for (int e = 0; e < EE; e++) a[e] += xv * sW[e * DD + lane + 32 * i];
    }
#pragma unroll
    for (int off = 16; off > 0; off >>= 1) {
#pragma unroll
        for (int e = 0; e < EE; e++)
            a[e] += __shfl_down_sync(0xffffffffu, a[e], off);
    }
    if (lane == 0) {
#pragma unroll
        for (int e = 0; e < EE; e++) a[e] += sbr[e];
        int e0 = 0; float m0 = a[0];
#pragma unroll
        for (int e = 1; e < EE; e++) if (a[e] > m0) { m0 = a[e]; e0 = e; }
        int e1 = -1; float m1 = -1e30f;
#pragma unroll
        for (int e = 0; e < EE; e++)
            if (e != e0 && a[e] > m1) { m1 = a[e]; e1 = e; }
        float d  = expf(m1 - m0);           // m1 <= m0
        float w0 = 1.f / (1.f + d);
        float w1 = d * w0;
        g_e0[t] = e0; g_e1[t] = e1;
        g_w0t[t] = w0; g_w1t[t] = w1;
        atomicAdd(&g_counts[e0], 1);
        atomicAdd(&g_counts[e1], 1);
    }
}

// ---------------------------------------------------------------------------
// Scan + scatter (expert-grouped slot lists, static tile table)
// ---------------------------------------------------------------------------
__global__ void k_scan() {
    int off = 0;
    for (int e = 0; e < EE; e++) {
        g_offsets[e] = off;
        g_cursor[e]  = off;
        off += g_counts[e];
        g_counts[e] = 0;
    }
    g_offsets[EE] = off;   // == SLOTS
    int nt = 0;
    for (int e = 0; e < EE; e++) {
        for (int r = g_offsets[e]; r < g_offsets[e + 1]; r += 128) {
            g_tile_e[nt]  = e;
            g_tile_r0[nt] = r;
            nt++;
        }
    }
    g_num_tiles = nt;
}

__global__ void k_scatter() {
    int t = blockIdx.x * 256 + threadIdx.x;
    int e0 = g_e0[t], e1 = g_e1[t];
    int p0 = atomicAdd(&g_cursor[e0], 1);
    g_slot_token[p0] = t; g_slot_w[p0] = g_w0t[t];
    int p1 = atomicAdd(&g_cursor[e1], 1);
    g_slot_token[p1] = t; g_slot_w[p1] = g_w1t[t];
}

// ---------------------------------------------------------------------------
// Converters (fp32 -> single fp16)
// ---------------------------------------------------------------------------
__global__ void k_convert_x(const float* __restrict__ x) {
    size_t i = ((size_t)blockIdx.x * 256 + threadIdx.x) * 4;
    float4 v = *reinterpret_cast<const float4*>(x + i);
    __half2 a; a.x = __float2half_rn(v.x); a.y = __float2half_rn(v.y);
    __half2 b; b.x = __float2half_rn(v.z); b.y = __float2half_rn(v.w);
    *reinterpret_cast<__half2*>(g_X + i)     = a;
    *reinterpret_cast<__half2*>(g_X + i + 2) = b;
}

__global__ void k_convert_w(const float* __restrict__ W1,
                            const float* __restrict__ W2) {
    size_t i = ((size_t)blockIdx.x * 256 + threadIdx.x) * 4;
    const size_t W1N = (size_t)EE * DD * FF;
    const float* src; __half* dst; size_t j;
    if (i < W1N) { src = W1; j = i;        dst = g_W1; }
    else         { src = W2; j = i - W1N;  dst = g_W2; }
    float4 v = *reinterpret_cast<const float4*>(src + j);
    __half2 a; a.x = __float2half_rn(v.x); a.y = __float2half_rn(v.y);
    __half2 b; b.x = __float2half_rn(v.z); b.y = __float2half_rn(v.w);
    *reinterpret_cast<__half2*>(dst + j)     = a;
    *reinterpret_cast<__half2*>(dst + j + 2) = b;
}

__global__ void k_zero(float* __restrict__ out) {
    size_t i = ((size_t)blockIdx.x * 256 + threadIdx.x) * 4;
    *reinterpret_cast<float4*>(out + i) = make_float4(0.f, 0.f, 0.f, 0.f);
}

// ---------------------------------------------------------------------------
// Grouped GEMM. MODE 0: H = relu(Xg @ W1[e] + b1[e]) -> fp16 scratch
//               MODE 1: out[token] += w * (H @ W2[e] + b2[e])   (atomicAdd)
// Tile: BM=128, BN=256, BK=64. 512 threads = 16 warps (4m x 4n), warp 32x64.
// Single fp16 operands, fp32 accumulate (1 MMA per acc tile).
// Smem/stage: A 16KB + B 32KB; 2 stages = 96KB.
// XOR swizzle on 16B chunks -> conflict-free ldmatrix.
// ---------------------------------------------------------------------------
constexpr int SMEM_BYTES = 98304;

template <int MODE>
__global__ void __launch_bounds__(512, 1) k_gemm(
    const float* __restrict__ bias, float* __restrict__ out) {
    constexpr int KDIM = MODE ? FF : DD;
    constexpr int NDIM = MODE ? DD : FF;
    constexpr int KT   = KDIM / 64;

    const int bid = blockIdx.x;
    if (bid >= g_num_tiles) return;
    const int e       = g_tile_e[bid];
    const int row0    = g_tile_r0[bid];
    const int seg_end = g_offsets[e + 1];
    const int n0      = blockIdx.y * 256;

    extern __shared__ char smem[];
    const uint32_t sA0 = smem_u32(smem);          // 2 x 16KB
    const uint32_t sB0 = sA0 + 32768;             // 2 x 32KB

    const int tid = threadIdx.x;
    const int lane = tid & 31, wid = tid >> 5;
    const int wm = wid >> 2, wn = wid & 3;        // 4 x 4 warps

    const __half* A = MODE ? g_H  : g_X;
    const __half* B = MODE ? g_W2 : g_W1;

    auto load_stage = [&](int ko, int st) {
        const int k0 = ko * 64;
        // A: 128 rows x 8 chunks (64 fp16 = 128B/row) = 1024 chunks, 2/thread
#pragma unroll
        for (int i = 0; i < 2; i++) {
            int c    = tid + i * 512;
            int row  = c >> 3;
            int kc   = c & 7;
            int phys = (kc ^ row) & 7;
            uint32_t s = sA0 + ((((st << 7) + row) << 3) + phys) * 16;
            int rg  = row0 + row;
            bool v  = rg < seg_end;
            size_t aidx;
            if (MODE == 0) {
                int tok = v ? g_slot_token[rg] : 0;
                aidx = (size_t)tok * DD + k0 + (kc << 3);
            } else {
                aidx = (size_t)(v ? rg : 0) * FF + k0 + (kc << 3);
            }
            cp16(s, A + aidx, v);
        }
        // B: 64 k-rows x 32 chunks (256 fp16 = 512B/row) = 2048 chunks, 4/thread
#pragma unroll
        for (int i = 0; i < 4; i++) {
            int c    = tid + i * 512;
            int kr   = c >> 5;
            int nc   = c & 31;
            int phys = (nc & 24) | ((nc ^ kr) & 7);
            uint32_t s = sB0 + (((st << 11) + (kr << 5) + phys)) * 16;
            size_t bidx = (size_t)e * KDIM * NDIM + (size_t)(k0 + kr) * NDIM
                        + n0 + (nc << 3);
            cp16(s, B + bidx, true);
        }
        cp_commit();
    };

    float acc[2][8][4];
#pragma unroll
    for (int a = 0; a < 2; a++)
#pragma unroll
        for (int b = 0; b < 8; b++)
#pragma unroll
            for (int c = 0; c < 4; c++) acc[a][b][c] = 0.f;

    load_stage(0, 0);
    int st = 0;
    for (int ko = 0; ko < KT; ko++) {
        if (ko + 1 < KT) load_stage(ko + 1, st ^ 1);
        else cp_commit();   // empty group so wait_group 1 drains the real one
        cp_wait1();
        __syncthreads();

#pragma unroll
        for (int ks = 0; ks < 4; ks++) {
            uint32_t af[2][4];
#pragma unroll
            for (int mt = 0; mt < 2; mt++) {
                int r  = wm * 32 + mt * 16 + (lane & 15);
                int kc = ks * 2 + (lane >> 4);
                int ph = (kc ^ r) & 7;
                ldsm_x4(af[mt], sA0 + ((((st << 7) + r) << 3) + ph) * 16);
            }
            uint32_t bf[16];
#pragma unroll
            for (int g = 0; g < 4; g++) {
                int kr = ks * 16 + (lane & 15);
                int nc = wn * 8 + g * 2 + (lane >> 4);
                int ph = (nc & 24) | ((nc ^ kr) & 7);
                ldsm_x4_t(&bf[g * 4],
                    sB0 + (((st << 11) + (kr << 5) + ph)) * 16);
            }
#pragma unroll
            for (int mt = 0; mt < 2; mt++)
#pragma unroll
                for (int nt = 0; nt < 8; nt++) {
                    int idx = (nt >> 1) * 4 + (nt & 1) * 2;
                    mma_f16(acc[mt][nt], af[mt], bf[idx], bf[idx + 1]);
                }
        }
        __syncthreads();
        st ^= 1;
    }

    // Epilogue
#pragma unroll
    for (int mt = 0; mt < 2; mt++) {
        int rr = wm * 32 + mt * 16 + (lane >> 2);
#pragma unroll
        for (int i = 0; i < 2; i++) {
            int rg = row0 + rr + i * 8;
            if (rg < seg_end) {
                if (MODE == 0) {
                    size_t base = (size_t)rg * FF;
#pragma unroll
                    for (int nt = 0; nt < 8; nt++) {
                        int col = n0 + wn * 64 + nt * 8 + ((lane & 3) << 1);
                        float v0 = acc[mt][nt][i * 2 + 0] + bias[e * NDIM + col];
                        float v1 = acc[mt][nt][i * 2 + 1] + bias[e * NDIM + col + 1];
                        __half2 hp;
                        hp.x = __float2half_rn(fmaxf(v0, 0.f));
                        hp.y = __float2half_rn(fmaxf(v1, 0.f));
                        *reinterpret_cast<__half2*>(g_H + base + col) = hp;
                    }
                } else {
                    int tok = g_slot_token[rg];
                    float w = g_slot_w[rg];
                    float* orow = out + (size_t)tok * DD;
#pragma unroll
                    for (int nt = 0; nt < 8; nt++) {
                        int col = n0 + wn * 64 + nt * 8 + ((lane & 3) << 1);
                        float v0 = (acc[mt][nt][i * 2 + 0] + bias[e * NDIM + col]) * w;
                        float v1 = (acc[mt][nt][i * 2 + 1] + bias[e * NDIM + col + 1]) * w;
                        atomicAdd(orow + col, v0);
                        atomicAdd(orow + col + 1, v1);
                    }
                }
            }
        }
    }
}

// ---------------------------------------------------------------------------
// Launch
// ---------------------------------------------------------------------------
extern "C" void kernel_launch(void* const* d_in, const int* in_sizes, int n_in,
                              void* d_out, int out_size) {
    const float* x  = (const float*)d_in[0];
    const float* Wr = (const float*)d_in[1];
    const float* br = (const float*)d_in[2];
    const float* W1 = (const float*)d_in[3];
    const float* b1 = (const float*)d_in[4];
    const float* W2 = (const float*)d_in[5];
    const float* b2 = (const float*)d_in[6];
    float* out = (float*)d_out;

    cudaFuncSetAttribute(k_gemm<0>, cudaFuncAttributeMaxDynamicSharedMemorySize,
                         SMEM_BYTES);
    cudaFuncSetAttribute(k_gemm<1>, cudaFuncAttributeMaxDynamicSharedMemorySize,
                         SMEM_BYTES);

    k_router<<<TT / 8, 256>>>(x, Wr, br);
    k_scan<<<1, 1>>>();
    k_scatter<<<TT / 256, 256>>>();
    k_convert_x<<<(TT * DD / 4) / 256, 256>>>(x);
    k_convert_w<<<(2 * EE * DD * FF / 4) / 256, 256>>>(W1, W2);
    k_zero<<<(TT * DD / 4) / 256, 256>>>(out);

    // GEMM1: 65536 x 2048, K=512 (grouped by expert)
    k_gemm<0><<<dim3(520, FF / 256), 512, SMEM_BYTES>>>(b1, nullptr);
    // GEMM2: 65536 x 512, K=2048 (grouped), scaled atomic accumulate
    k_gemm<1><<<dim3(520, DD / 256), 512, SMEM_BYTES>>>(b2, out);
}

// round 8
// speedup vs baseline: 2.6619x; 1.1133x over previous
#include <cuda_runtime.h>
#include <cuda_fp16.h>
#include <cstdint>
#include <cstddef>

// Problem constants
#define TT 32768      // tokens (B*S)
#define DD 512        // model dim
#define FF 2048       // ffn dim
#define EE 8          // experts
#define SLOTS 65536   // TT * K(=2)

// ---------------------------------------------------------------------------
// Device scratch (allocation-free rule: __device__ globals).
// Referenced ONLY from device code (host use would hit ATS host-shadow zeros).
// ---------------------------------------------------------------------------
__device__ __align__(256) int   g_e0[TT], g_e1[TT];
__device__ __align__(256) float g_w0t[TT], g_w1t[TT];
__device__ __align__(256) int   g_counts[EE];
__device__ __align__(256) int   g_offsets[EE + 1];
__device__ __align__(256) int   g_cursor[EE];
__device__ __align__(256) int   g_tile_e[528], g_tile_r0[528];
__device__ __align__(256) int   g_num_tiles;
__device__ __align__(256) int   g_slot_token[SLOTS];
__device__ __align__(256) float g_slot_w[SLOTS];

// fp16 operand scratch (single precision operands; fp32 accumulate in MMA)
__device__ __align__(256) __half g_X [(size_t)TT * DD];
__device__ __align__(256) __half g_W1[(size_t)EE * DD * FF];
__device__ __align__(256) __half g_W2[(size_t)EE * FF * DD];
__device__ __align__(256) __half g_H [(size_t)SLOTS * FF];

// ---------------------------------------------------------------------------
// PTX helpers
// ---------------------------------------------------------------------------
__device__ __forceinline__ uint32_t smem_u32(const void* p) {
    uint32_t a;
    asm("{ .reg .u64 t; cvta.to.shared.u64 t, %1; cvt.u32.u64 %0, t; }"
        : "=r"(a) : "l"(p));
    return a;
}

__device__ __forceinline__ void cp16(uint32_t s, const void* g, bool valid) {
    int sz = valid ? 16 : 0;
    asm volatile("cp.async.cg.shared.global [%0], [%1], 16, %2;\n"
                 :: "r"(s), "l"(__cvta_generic_to_global(g)), "r"(sz));
}
__device__ __forceinline__ void cp_commit() {
    asm volatile("cp.async.commit_group;\n" ::);
}
__device__ __forceinline__ void cp_wait1() {
    asm volatile("cp.async.wait_group 1;\n" ::);
}

__device__ __forceinline__ void ldsm_x4(uint32_t* r, uint32_t addr) {
    asm volatile("ldmatrix.sync.aligned.m8n8.x4.shared.b16 {%0,%1,%2,%3}, [%4];"
                 : "=r"(r[0]), "=r"(r[1]), "=r"(r[2]), "=r"(r[3]) : "r"(addr));
}
__device__ __forceinline__ void ldsm_x4_t(uint32_t* r, uint32_t addr) {
    asm volatile("ldmatrix.sync.aligned.m8n8.x4.trans.shared.b16 {%0,%1,%2,%3}, [%4];"
                 : "=r"(r[0]), "=r"(r[1]), "=r"(r[2]), "=r"(r[3]) : "r"(addr));
}

__device__ __forceinline__ void mma_f16(float* d, const uint32_t* a,
                                        uint32_t b0, uint32_t b1) {
    asm volatile(
        "mma.sync.aligned.m16n8k16.row.col.f32.f16.f16.f32 "
        "{%0,%1,%2,%3}, {%4,%5,%6,%7}, {%8,%9}, {%0,%1,%2,%3};\n"
        : "+f"(d[0]), "+f"(d[1]), "+f"(d[2]), "+f"(d[3])
        : "r"(a[0]), "r"(a[1]), "r"(a[2]), "r"(a[3]), "r"(b0), "r"(b1));
}

// ---------------------------------------------------------------------------
// Router: logits = x @ Wr + br ; top-2 ; renormalized softmax weights
// ---------------------------------------------------------------------------
__global__ void k_router(const float* __restrict__ x,
                         const float* __restrict__ Wr,
                         const float* __restrict__ br) {
    __shared__ float sW[EE * DD];   // transposed: sW[e*512 + d]
    __shared__ float sbr[EE];
    const int tid = threadIdx.x;
    for (int i = tid; i < EE * DD; i += 256) {
        int e = i >> 9, d = i & 511;
        sW[i] = Wr[d * EE + e];
    }
    if (tid < EE) sbr[tid] = br[tid];
    __syncthreads();

    const int lane = tid & 31, wid = tid >> 5;
    const int t = blockIdx.x * 8 + wid;
    const float* xr = x + (size_t)t * DD;

    float a[EE];
#pragma unroll
    for (int e = 0; e < EE; e++) a[e] = 0.f;
#pragma unroll
    for (int i = 0; i < 16; i++) {
        float xv = xr[lane + 32 * i];
#pragma unroll
        for (int e = 0; e < EE; e++) a[e] += xv * sW[e * DD + lane + 32 * i];
    }
#pragma unroll
    for (int off = 16; off > 0; off >>= 1) {
#pragma unroll
        for (int e = 0; e < EE; e++)
            a[e] += __shfl_down_sync(0xffffffffu, a[e], off);
    }
    if (lane == 0) {
#pragma unroll
        for (int e = 0; e < EE; e++) a[e] += sbr[e];
        int e0 = 0; float m0 = a[0];
#pragma unroll
        for (int e = 1; e < EE; e++) if (a[e] > m0) { m0 = a[e]; e0 = e; }
        int e1 = -1; float m1 = -1e30f;
#pragma unroll
        for (int e = 0; e < EE; e++)
            if (e != e0 && a[e] > m1) { m1 = a[e]; e1 = e; }
        float d  = expf(m1 - m0);           // m1 <= m0
        float w0 = 1.f / (1.f + d);
        float w1 = d * w0;
        g_e0[t] = e0; g_e1[t] = e1;
        g_w0t[t] = w0; g_w1t[t] = w1;
        atomicAdd(&g_counts[e0], 1);
        atomicAdd(&g_counts[e1], 1);
    }
}

// ---------------------------------------------------------------------------
// Scan + scatter (expert-grouped slot lists, static tile table)
// ---------------------------------------------------------------------------
__global__ void k_scan() {
    int off = 0;
    for (int e = 0; e < EE; e++) {
        g_offsets[e] = off;
        g_cursor[e]  = off;
        off += g_counts[e];
        g_counts[e] = 0;
    }
    g_offsets[EE] = off;   // == SLOTS
    int nt = 0;
    for (int e = 0; e < EE; e++)
        for (int r = g_offsets[e]; r < g_offsets[e + 1]; r += 128) {
            g_tile_e[nt] = e; g_tile_r0[nt] = r; nt++;
        }
    g_num_tiles = nt;
}

__global__ void k_scatter() {
    int t = blockIdx.x * 256 + threadIdx.x;
    int e0 = g_e0[t], e1 = g_e1[t];
    int p0 = atomicAdd(&g_cursor[e0], 1);
    g_slot_token[p0] = t; g_slot_w[p0] = g_w0t[t];
    int p1 = atomicAdd(&g_cursor[e1], 1);
    g_slot_token[p1] = t; g_slot_w[p1] = g_w1t[t];
}

// ---------------------------------------------------------------------------
// Converters (fp32 -> single fp16)
// ---------------------------------------------------------------------------
__global__ void k_convert_x(const float* __restrict__ x) {
    size_t i = ((size_t)blockIdx.x * 256 + threadIdx.x) * 4;
    float4 v = *reinterpret_cast<const float4*>(x + i);
    __half2 a; a.x = __float2half_rn(v.x); a.y = __float2half_rn(v.y);
    __half2 b; b.x = __float2half_rn(v.z); b.y = __float2half_rn(v.w);
    *reinterpret_cast<__half2*>(g_X + i)     = a;
    *reinterpret_cast<__half2*>(g_X + i + 2) = b;
}

__global__ void k_convert_w(const float* __restrict__ W1,
                            const float* __restrict__ W2) {
    size_t i = ((size_t)blockIdx.x * 256 + threadIdx.x) * 4;
    const size_t W1N = (size_t)EE * DD * FF;
    const float* src; __half* dst; size_t j;
    if (i < W1N) { src = W1; j = i;        dst = g_W1; }
    else         { src = W2; j = i - W1N;  dst = g_W2; }
    float4 v = *reinterpret_cast<const float4*>(src + j);
    __half2 a; a.x = __float2half_rn(v.x); a.y = __float2half_rn(v.y);
    __half2 b; b.x = __float2half_rn(v.z); b.y = __float2half_rn(v.w);
    *reinterpret_cast<__half2*>(dst + j)     = a;
    *reinterpret_cast<__half2*>(dst + j + 2) = b;
}

__global__ void k_zero(float* __restrict__ out) {
    size_t i = ((size_t)blockIdx.x * 256 + threadIdx.x) * 4;
    *reinterpret_cast<float4*>(out + i) = make_float4(0.f, 0.f, 0.f, 0.f);
}

// ---------------------------------------------------------------------------
// Grouped GEMM. MODE 0: H = relu(Xg @ W1[e] + b1[e]) -> fp16 scratch
//               MODE 1: out[token] += w * (H @ W2[e] + b2[e])   (atomicAdd)
// Tile: BM=128, BN=128, BK=64. 256 threads = 8 warps (4m x 2n), warp 32x64.
// 3-stage cp.async pipeline (stage index = k-iter % 3 — the round-7 OOB bug
// was `ld-3` here), ONE __syncthreads per k-iter, 2 CTAs/SM.
// XOR swizzle on 16B chunks -> conflict-free ldmatrix.
// ---------------------------------------------------------------------------
constexpr int SMEM_BYTES = 3 * (16384 + 16384);   // 96KB

template <int MODE>
__global__ void __launch_bounds__(256, 2) k_gemm(
    const float* __restrict__ bias, float* __restrict__ out) {
    constexpr int KDIM = MODE ? FF : DD;
    constexpr int NDIM = MODE ? DD : FF;
    constexpr int KT   = KDIM / 64;

    const int bid = blockIdx.x;
    if (bid >= g_num_tiles) return;
    const int e       = g_tile_e[bid];
    const int row0    = g_tile_r0[bid];
    const int seg_end = g_offsets[e + 1];
    const int n0      = blockIdx.y * 128;

    extern __shared__ char smem[];
    const uint32_t sA0 = smem_u32(smem);          // 3 x 16KB
    const uint32_t sB0 = sA0 + 3 * 16384;         // 3 x 16KB

    const int tid = threadIdx.x;
    const int lane = tid & 31, wid = tid >> 5;
    const int wm = wid >> 1, wn = wid & 1;        // 4m x 2n

    const __half* A = MODE ? g_H  : g_X;
    const __half* B = MODE ? g_W2 : g_W1;

    auto load_stage = [&](int ko, int st) {
        const int k0 = ko * 64;
        // A: 128 rows x 8 chunks of 16B (128B/row) = 1024 chunks, 4/thread
#pragma unroll
        for (int i = 0; i < 4; i++) {
            int c    = tid + i * 256;
            int row  = c >> 3;
            int kc   = c & 7;
            int phys = (kc ^ row) & 7;
            uint32_t s = sA0 + st * 16384 + row * 128 + phys * 16;
            int rg  = row0 + row;
            bool v  = rg < seg_end;
            size_t aidx;
            if (MODE == 0) {
                int tok = v ? g_slot_token[rg] : 0;
                aidx = (size_t)tok * DD + k0 + (kc << 3);
            } else {
                aidx = (size_t)(v ? rg : 0) * FF + k0 + (kc << 3);
            }
            cp16(s, A + aidx, v);
        }
        // B: 64 k-rows x 16 chunks (128 fp16 = 256B/row) = 1024 chunks, 4/thread
#pragma unroll
        for (int i = 0; i < 4; i++) {
            int c    = tid + i * 256;
            int kr   = c >> 4;
            int nc   = c & 15;
            int phys = (nc & 8) | ((nc ^ kr) & 7);
            uint32_t s = sB0 + st * 16384 + kr * 256 + phys * 16;
            size_t bidx = (size_t)e * KDIM * NDIM + (size_t)(k0 + kr) * NDIM
                        + n0 + (nc << 3);
            cp16(s, B + bidx, true);
        }
        cp_commit();
    };

    float acc[2][8][4];
#pragma unroll
    for (int a = 0; a < 2; a++)
#pragma unroll
        for (int b = 0; b < 8; b++)
#pragma unroll
            for (int c = 0; c < 4; c++) acc[a][b][c] = 0.f;

    load_stage(0, 0);
    load_stage(1, 1);
    int st = 0;
    for (int ko = 0; ko < KT; ko++) {
        cp_wait1();          // stage ko resident (<=1 group outstanding)
        __syncthreads();     // all warps done with stage (ko-1)%3 slot too

        int ld = ko + 2;
        if (ld < KT) load_stage(ld, ld % 3);   // FIX: modulo, not subtract-once
        else cp_commit();    // empty group keeps wait_group(1) accounting

#pragma unroll
        for (int ks = 0; ks < 4; ks++) {
            uint32_t af[2][4];
#pragma unroll
            for (int mt = 0; mt < 2; mt++) {
                int r  = wm * 32 + mt * 16 + (lane & 15);
                int kc = ks * 2 + (lane >> 4);
                int ph = (kc ^ r) & 7;
                ldsm_x4(af[mt], sA0 + st * 16384 + r * 128 + ph * 16);
            }
            uint32_t bf[16];
#pragma unroll
            for (int g = 0; g < 4; g++) {
                int kr = ks * 16 + (lane & 15);
                int nc = wn * 8 + g * 2 + (lane >> 4);
                int ph = (nc & 8) | ((nc ^ kr) & 7);
                ldsm_x4_t(&bf[g * 4], sB0 + st * 16384 + kr * 256 + ph * 16);
            }
#pragma unroll
            for (int mt = 0; mt < 2; mt++)
#pragma unroll
                for (int nt = 0; nt < 8; nt++) {
                    int idx = (nt >> 1) * 4 + (nt & 1) * 2;
                    mma_f16(acc[mt][nt], af[mt], bf[idx], bf[idx + 1]);
                }
        }
        st = (st == 2) ? 0 : st + 1;
    }

    // Epilogue
#pragma unroll
    for (int mt = 0; mt < 2; mt++) {
        int rr = wm * 32 + mt * 16 + (lane >> 2);
#pragma unroll
        for (int i = 0; i < 2; i++) {
            int rg = row0 + rr + i * 8;
            if (rg < seg_end) {
                if (MODE == 0) {
                    size_t base = (size_t)rg * FF;
#pragma unroll
                    for (int nt = 0; nt < 8; nt++) {
                        int col = n0 + wn * 64 + nt * 8 + ((lane & 3) << 1);
                        float v0 = acc[mt][nt][i * 2 + 0] + bias[e * NDIM + col];
                        float v1 = acc[mt][nt][i * 2 + 1] + bias[e * NDIM + col + 1];
                        __half2 hp;
                        hp.x = __float2half_rn(fmaxf(v0, 0.f));
                        hp.y = __float2half_rn(fmaxf(v1, 0.f));
                        *reinterpret_cast<__half2*>(g_H + base + col) = hp;
                    }
                } else {
                    int tok = g_slot_token[rg];
                    float w = g_slot_w[rg];
                    float* orow = out + (size_t)tok * DD;
#pragma unroll
                    for (int nt = 0; nt < 8; nt++) {
                        int col = n0 + wn * 64 + nt * 8 + ((lane & 3) << 1);
                        float v0 = (acc[mt][nt][i * 2 + 0] + bias[e * NDIM + col]) * w;
                        float v1 = (acc[mt][nt][i * 2 + 1] + bias[e * NDIM + col + 1]) * w;
                        atomicAdd(orow + col, v0);
                        atomicAdd(orow + col + 1, v1);
                    }
                }
            }
        }
    }
}

// ---------------------------------------------------------------------------
// Launch
// ---------------------------------------------------------------------------
extern "C" void kernel_launch(void* const* d_in, const int* in_sizes, int n_in,
                              void* d_out, int out_size) {
    const float* x  = (const float*)d_in[0];
    const float* Wr = (const float*)d_in[1];
    const float* br = (const float*)d_in[2];
    const float* W1 = (const float*)d_in[3];
    const float* b1 = (const float*)d_in[4];
    const float* W2 = (const float*)d_in[5];
    const float* b2 = (const float*)d_in[6];
    float* out = (float*)d_out;

    cudaFuncSetAttribute(k_gemm<0>, cudaFuncAttributeMaxDynamicSharedMemorySize,
                         SMEM_BYTES);
    cudaFuncSetAttribute(k_gemm<1>, cudaFuncAttributeMaxDynamicSharedMemorySize,
                         SMEM_BYTES);

    k_router<<<TT / 8, 256>>>(x, Wr, br);
    k_scan<<<1, 1>>>();
    k_scatter<<<TT / 256, 256>>>();
    k_convert_x<<<(TT * DD / 4) / 256, 256>>>(x);
    k_convert_w<<<(2 * EE * DD * FF / 4) / 256, 256>>>(W1, W2);
    k_zero<<<(TT * DD / 4) / 256, 256>>>(out);

    // GEMM1: 65536 x 2048, K=512 (grouped by expert)
    k_gemm<0><<<dim3(520, FF / 128), 256, SMEM_BYTES>>>(b1, nullptr);
    // GEMM2: 65536 x 512, K=2048 (grouped), scaled atomic accumulate
    k_gemm<1><<<dim3(520, DD / 128), 256, SMEM_BYTES>>>(b2, out);
}